// round 2
// baseline (speedup 1.0000x reference)
#include <cuda_runtime.h>
#include <math.h>

#define CB    8
#define C2    96
#define H2    112
#define LTOK  12544
#define NWB   2048
#define HID   384

__device__ float d_bufX[CB*LTOK*C2];
__device__ float d_bufW[CB*LTOK*C2];
__device__ float d_bufA[CB*LTOK*C2];
__device__ float d_bufQ[NWB*3*6*49*16];
__device__ float d_bufH[CB*LTOK*HID];
__device__ float d_wc[4*96*768];
__device__ float d_cscale[96];
__device__ float d_cshift[96];

__global__ void prep_kernel(const float* __restrict__ up_w, const float* __restrict__ up_b,
                            const float* __restrict__ bn_g, const float* __restrict__ bn_b,
                            const float* __restrict__ bn_m, const float* __restrict__ bn_v) {
    int tid = blockIdx.x * blockDim.x + threadIdx.x;
    if (tid < 96) {
        float s = bn_g[tid] * rsqrtf(bn_v[tid] + 1e-5f);
        d_cscale[tid] = s;
        d_cshift[tid] = (up_b[tid] - bn_m[tid]) * s + bn_b[tid];
    }
    int total = 4 * 96 * 192;
    for (int idx = tid; idx < total; idx += gridDim.x * blockDim.x) {
        int p  = idx / (96 * 192);
        int r  = idx % (96 * 192);
        int co = r / 192, ci = r % 192;
        int py = p >> 1, px = p & 1;
        const float* w = up_w + ((size_t)co * 192 + ci) * 9;
        float cs[3][2];
        #pragma unroll
        for (int ky = 0; ky < 3; ky++) {
            float w0 = w[ky*3], w1 = w[ky*3+1], w2 = w[ky*3+2];
            cs[ky][0] = (px == 0) ? w0 : (w0 + w1);
            cs[ky][1] = (px == 0) ? (w1 + w2) : w2;
        }
        float* dst = d_wc + ((size_t)p * 96 + co) * 768 + ci * 4;
        #pragma unroll
        for (int b2 = 0; b2 < 2; b2++) {
            dst[b2]     = (py == 0) ? cs[0][b2] : (cs[0][b2] + cs[1][b2]);
            dst[2 + b2] = (py == 0) ? (cs[1][b2] + cs[2][b2]) : cs[2][b2];
        }
    }
}

struct ALDirect {
    const float* A; int K;
    struct Ctx { const float* p; };
    __device__ Ctx prep(int m) const { Ctx c; c.p = A + (size_t)m * K; return c; }
    __device__ float4 load(const Ctx& c, int k) const { return *(const float4*)(c.p + k); }
};

struct ALConv {
    const float* in; int py, px;
    struct Ctx { const float* base; int o0, o1, o2, o3; };
    __device__ Ctx prep(int m) const {
        int b = m / 3136, r = m - b * 3136;
        int ty = r / 56, tx = r - ty * 56;
        int r0 = ty - 1 + py, r1 = r0 + 1;
        int c0 = tx - 1 + px, c1 = c0 + 1;
        bool r0v = (unsigned)r0 < 56u, r1v = (unsigned)r1 < 56u;
        bool c0v = (unsigned)c0 < 56u, c1v = (unsigned)c1 < 56u;
        Ctx c;
        c.base = in + (size_t)b * 192 * 3136;
        c.o0 = (r0v && c0v) ? r0 * 56 + c0 : -1;
        c.o1 = (r0v && c1v) ? r0 * 56 + c1 : -1;
        c.o2 = (r1v && c0v) ? r1 * 56 + c0 : -1;
        c.o3 = (r1v && c1v) ? r1 * 56 + c1 : -1;
        return c;
    }
    __device__ float4 load(const Ctx& c, int k) const {
        const float* p = c.base + (size_t)(k >> 2) * 3136;
        float4 v;
        v.x = (c.o0 >= 0) ? p[c.o0] : 0.f;
        v.y = (c.o1 >= 0) ? p[c.o1] : 0.f;
        v.z = (c.o2 >= 0) ? p[c.o2] : 0.f;
        v.w = (c.o3 >= 0) ? p[c.o3] : 0.f;
        return v;
    }
};

struct StConv {
    float* out; const float* scale; const float* shift; int py, px;
    __device__ void store(int m, int n, float v) const {
        v = fmaxf(v * scale[n] + shift[n], 0.f);
        int b = m / 3136, r = m - b * 3136;
        int ty = r / 56, tx = r - ty * 56;
        int y = 2 * ty + py, x = 2 * tx + px;
        out[((size_t)b * LTOK + y * H2 + x) * C2 + n] = v;
    }
};
struct StQKV {
    float* out; const float* bias;
    __device__ void store(int m, int n, float v) const {
        v += bias[n];
        int s3 = n / 96, rem = n - s3 * 96;
        int h = rem >> 4, d = rem & 15;
        if (s3 == 0) v *= 0.25f;
        int bw = m / 49, nn = m - bw * 49;
        out[(((size_t)(bw * 3 + s3) * 6 + h) * 49 + nn) * 16 + d] = v;
    }
};
struct StProj {
    float* out; const float* bias; int shift;
    __device__ void store(int m, int n, float v) const {
        int bw = m / 49, nn = m - bw * 49;
        int b = bw >> 8, wy = (bw >> 4) & 15, wx = bw & 15;
        int iy = nn / 7, ix = nn - iy * 7;
        int y = wy * 7 + iy + shift; if (y >= H2) y -= H2;
        int x = wx * 7 + ix + shift; if (x >= H2) x -= H2;
        out[((size_t)b * LTOK + y * H2 + x) * C2 + n] += v + bias[n];
    }
};
struct StGelu {
    float* out; const float* bias;
    __device__ void store(int m, int n, float v) const {
        v += bias[n];
        v = 0.5f * v * (1.0f + erff(v * 0.70710678118654752f));
        out[(size_t)m * HID + n] = v;
    }
};
struct StFC2 {
    float* out; const float* bias;
    __device__ void store(int m, int n, float v) const {
        out[(size_t)m * C2 + n] += v + bias[n];
    }
};
struct StOut {
    float* out; const float* bias;
    __device__ void store(int m, int n, float v) const {
        v = fmaxf(v + bias[n], 0.f);
        int b = m / LTOK, pix = m - b * LTOK;
        out[((size_t)b * 48 + n) * LTOK + pix] = v;
    }
};

template<class AL, class ST>
__global__ void __launch_bounds__(128) gemm_k(AL al, ST st,
                                              const float* __restrict__ Bw,
                                              int N, int K) {
    __shared__ float As[16][64];
    __shared__ float Bs[16][64];
    const int tid = threadIdx.x;
    const int m0 = blockIdx.x << 6, n0 = blockIdx.y << 6;
    const int trow = tid >> 4, tcol = tid & 15;
    const int mm0 = tid >> 2, mm1 = (tid + 128) >> 2;
    const int kq4 = (tid & 3) << 2;
    typename AL::Ctx ctx0 = al.prep(m0 + mm0);
    typename AL::Ctx ctx1 = al.prep(m0 + mm1);

    float acc[8][4];
    #pragma unroll
    for (int i = 0; i < 8; i++)
        #pragma unroll
        for (int j = 0; j < 4; j++) acc[i][j] = 0.f;

    for (int k0 = 0; k0 < K; k0 += 16) {
        float4 a0v = al.load(ctx0, k0 + kq4);
        float4 a1v = al.load(ctx1, k0 + kq4);
        float4 b0v = make_float4(0.f,0.f,0.f,0.f), b1v = make_float4(0.f,0.f,0.f,0.f);
        if (n0 + mm0 < N) b0v = *(const float4*)(Bw + (size_t)(n0 + mm0) * K + k0 + kq4);
        if (n0 + mm1 < N) b1v = *(const float4*)(Bw + (size_t)(n0 + mm1) * K + k0 + kq4);
        __syncthreads();
        As[kq4+0][mm0]=a0v.x; As[kq4+1][mm0]=a0v.y; As[kq4+2][mm0]=a0v.z; As[kq4+3][mm0]=a0v.w;
        As[kq4+0][mm1]=a1v.x; As[kq4+1][mm1]=a1v.y; As[kq4+2][mm1]=a1v.z; As[kq4+3][mm1]=a1v.w;
        Bs[kq4+0][mm0]=b0v.x; Bs[kq4+1][mm0]=b0v.y; Bs[kq4+2][mm0]=b0v.z; Bs[kq4+3][mm0]=b0v.w;
        Bs[kq4+0][mm1]=b1v.x; Bs[kq4+1][mm1]=b1v.y; Bs[kq4+2][mm1]=b1v.z; Bs[kq4+3][mm1]=b1v.w;
        __syncthreads();
        #pragma unroll
        for (int kk = 0; kk < 16; kk++) {
            float4 aa0 = *(const float4*)(&As[kk][trow << 3]);
            float4 aa1 = *(const float4*)(&As[kk][(trow << 3) + 4]);
            float4 bb  = *(const float4*)(&Bs[kk][tcol << 2]);
            float av[8] = {aa0.x,aa0.y,aa0.z,aa0.w,aa1.x,aa1.y,aa1.z,aa1.w};
            float bv[4] = {bb.x,bb.y,bb.z,bb.w};
            #pragma unroll
            for (int i = 0; i < 8; i++)
                #pragma unroll
                for (int j = 0; j < 4; j++) acc[i][j] += av[i] * bv[j];
        }
    }
    #pragma unroll
    for (int i = 0; i < 8; i++) {
        int m = m0 + (trow << 3) + i;
        #pragma unroll
        for (int j = 0; j < 4; j++) {
            int n = n0 + (tcol << 2) + j;
            if (n < N) st.store(m, n, acc[i][j]);
        }
    }
}

__device__ __forceinline__ float warp_sum(float v) {
    #pragma unroll
    for (int o = 16; o; o >>= 1) v += __shfl_xor_sync(0xffffffffu, v, o);
    return v;
}

__global__ void __launch_bounds__(128) ln_part_kernel(const float* __restrict__ src,
                                                      float* __restrict__ dst,
                                                      const float* __restrict__ g,
                                                      const float* __restrict__ be,
                                                      int shift) {
    int warp = threadIdx.x >> 5, lane = threadIdx.x & 31;
    int gidx = blockIdx.x * 4 + warp;
    int bw = gidx / 49, nn = gidx - bw * 49;
    int b = bw >> 8, wy = (bw >> 4) & 15, wx = bw & 15;
    int iy = nn / 7, ix = nn - iy * 7;
    int ys = wy * 7 + iy + shift; if (ys >= H2) ys -= H2;
    int xs = wx * 7 + ix + shift; if (xs >= H2) xs -= H2;
    const float* sp = src + ((size_t)b * LTOK + ys * H2 + xs) * C2;
    float v0 = sp[lane], v1 = sp[lane + 32], v2 = sp[lane + 64];
    float mean = warp_sum(v0 + v1 + v2) * (1.f / 96.f);
    float d0 = v0 - mean, d1 = v1 - mean, d2 = v2 - mean;
    float var = warp_sum(d0*d0 + d1*d1 + d2*d2) * (1.f / 96.f);
    float inv = rsqrtf(var + 1e-5f);
    float* dp = dst + (size_t)gidx * C2;
    dp[lane]      = d0 * inv * g[lane]      + be[lane];
    dp[lane + 32] = d1 * inv * g[lane + 32] + be[lane + 32];
    dp[lane + 64] = d2 * inv * g[lane + 64] + be[lane + 64];
}

__global__ void __launch_bounds__(128) ln_plain_kernel(const float* __restrict__ src,
                                                       float* __restrict__ dst,
                                                       const float* __restrict__ g,
                                                       const float* __restrict__ be) {
    int warp = threadIdx.x >> 5, lane = threadIdx.x & 31;
    size_t gidx = (size_t)blockIdx.x * 4 + warp;
    const float* sp = src + gidx * C2;
    float v0 = sp[lane], v1 = sp[lane + 32], v2 = sp[lane + 64];
    float mean = warp_sum(v0 + v1 + v2) * (1.f / 96.f);
    float d0 = v0 - mean, d1 = v1 - mean, d2 = v2 - mean;
    float var = warp_sum(d0*d0 + d1*d1 + d2*d2) * (1.f / 96.f);
    float inv = rsqrtf(var + 1e-5f);
    float* dp = dst + gidx * C2;
    dp[lane]      = d0 * inv * g[lane]      + be[lane];
    dp[lane + 32] = d1 * inv * g[lane + 32] + be[lane + 32];
    dp[lane + 64] = d2 * inv * g[lane + 64] + be[lane + 64];
}

__global__ void __launch_bounds__(64) attn_kernel(const float* __restrict__ qkv,
                                                  const float* __restrict__ rel,
                                                  float* __restrict__ outA,
                                                  int shifted) {
    __shared__ float sq[784], sk[784], sv[784], srel[169];
    __shared__ float sp[49 * 49];
    __shared__ int slbl[49];
    int bw = blockIdx.x, h = blockIdx.y;
    int tid = threadIdx.x;
    const float* qb = qkv + ((size_t)(bw * 3 + 0) * 6 + h) * 784;
    const float* kb = qkv + ((size_t)(bw * 3 + 1) * 6 + h) * 784;
    const float* vb = qkv + ((size_t)(bw * 3 + 2) * 6 + h) * 784;
    for (int i = tid; i < 784; i += 64) { sq[i] = qb[i]; sk[i] = kb[i]; sv[i] = vb[i]; }
    for (int i = tid; i < 169; i += 64) srel[i] = rel[i * 6 + h];
    if (tid < 49) {
        if (shifted) {
            int wy = (bw >> 4) & 15, wx = bw & 15;
            int yy = wy * 7 + tid / 7, xx = wx * 7 + tid % 7;
            int ry = (yy < 105) ? 0 : ((yy < 109) ? 1 : 2);
            int rx = (xx < 105) ? 0 : ((xx < 109) ? 1 : 2);
            slbl[tid] = ry * 3 + rx;
        } else slbl[tid] = 0;
    }
    __syncthreads();
    if (tid < 49) {
        int iy = tid / 7, ix = tid - iy * 7;
        float4 q0 = *(const float4*)&sq[tid*16+0];
        float4 q1 = *(const float4*)&sq[tid*16+4];
        float4 q2 = *(const float4*)&sq[tid*16+8];
        float4 q3 = *(const float4*)&sq[tid*16+12];
        int mylbl = slbl[tid];
        float mx = -1e30f;
        int jy = 0, jx = 0;
        for (int m = 0; m < 49; m++) {
            float4 k0 = *(const float4*)&sk[m*16+0];
            float4 k1 = *(const float4*)&sk[m*16+4];
            float4 k2 = *(const float4*)&sk[m*16+8];
            float4 k3 = *(const float4*)&sk[m*16+12];
            float d = q0.x*k0.x+q0.y*k0.y+q0.z*k0.z+q0.w*k0.w
                    + q1.x*k1.x+q1.y*k1.y+q1.z*k1.z+q1.w*k1.w
                    + q2.x*k2.x+q2.y*k2.y+q2.z*k2.z+q2.w*k2.w
                    + q3.x*k3.x+q3.y*k3.y+q3.z*k3.z+q3.w*k3.w;
            d += srel[(iy - jy + 6) * 13 + (ix - jx + 6)];
            if (shifted && slbl[m] != mylbl) d -= 100.f;
            sp[tid * 49 + m] = d;
            mx = fmaxf(mx, d);
            if (++jx == 7) { jx = 0; ++jy; }
        }
        float sum = 0.f;
        for (int m = 0; m < 49; m++) {
            float e = __expf(sp[tid * 49 + m] - mx);
            sp[tid * 49 + m] = e;
            sum += e;
        }
        float inv = 1.f / sum;
        float o[16];
        #pragma unroll
        for (int d = 0; d < 16; d++) o[d] = 0.f;
        for (int m = 0; m < 49; m++) {
            float p = sp[tid * 49 + m] * inv;
            float4 v0 = *(const float4*)&sv[m*16+0];
            float4 v1 = *(const float4*)&sv[m*16+4];
            float4 v2 = *(const float4*)&sv[m*16+8];
            float4 v3 = *(const float4*)&sv[m*16+12];
            o[0]+=p*v0.x; o[1]+=p*v0.y; o[2]+=p*v0.z; o[3]+=p*v0.w;
            o[4]+=p*v1.x; o[5]+=p*v1.y; o[6]+=p*v1.z; o[7]+=p*v1.w;
            o[8]+=p*v2.x; o[9]+=p*v2.y; o[10]+=p*v2.z; o[11]+=p*v2.w;
            o[12]+=p*v3.x; o[13]+=p*v3.y; o[14]+=p*v3.z; o[15]+=p*v3.w;
        }
        float* op = outA + ((size_t)bw * 49 + tid) * C2 + h * 16;
        *(float4*)(op+0)  = make_float4(o[0],o[1],o[2],o[3]);
        *(float4*)(op+4)  = make_float4(o[4],o[5],o[6],o[7]);
        *(float4*)(op+8)  = make_float4(o[8],o[9],o[10],o[11]);
        *(float4*)(op+12) = make_float4(o[12],o[13],o[14],o[15]);
    }
}

extern "C" void kernel_launch(void* const* d_in, const int* in_sizes, int n_in,
                              void* d_out, int out_size) {
    (void)in_sizes; (void)n_in; (void)out_size;
    const float* x     = (const float*)d_in[0];
    const float* up_w  = (const float*)d_in[1];
    const float* up_b  = (const float*)d_in[2];
    const float* bn_g  = (const float*)d_in[3];
    const float* bn_b  = (const float*)d_in[4];
    const float* bn_m  = (const float*)d_in[5];
    const float* bn_v  = (const float*)d_in[6];
    const float* n1g   = (const float*)d_in[7];
    const float* n1b   = (const float*)d_in[8];
    const float* qkvw  = (const float*)d_in[9];
    const float* qkvb  = (const float*)d_in[10];
    const float* projw = (const float*)d_in[11];
    const float* projb = (const float*)d_in[12];
    const float* rel   = (const float*)d_in[13];
    const float* n2g   = (const float*)d_in[14];
    const float* n2b   = (const float*)d_in[15];
    const float* f1w   = (const float*)d_in[16];
    const float* f1b   = (const float*)d_in[17];
    const float* f2w   = (const float*)d_in[18];
    const float* f2b   = (const float*)d_in[19];
    const float* outw  = (const float*)d_in[20];
    const float* outb  = (const float*)d_in[21];
    float* out = (float*)d_out;

    float *bX, *bW, *bA, *bQ, *bH, *wc, *scl, *sft;
    cudaGetSymbolAddress((void**)&bX,  d_bufX);
    cudaGetSymbolAddress((void**)&bW,  d_bufW);
    cudaGetSymbolAddress((void**)&bA,  d_bufA);
    cudaGetSymbolAddress((void**)&bQ,  d_bufQ);
    cudaGetSymbolAddress((void**)&bH,  d_bufH);
    cudaGetSymbolAddress((void**)&wc,  d_wc);
    cudaGetSymbolAddress((void**)&scl, d_cscale);
    cudaGetSymbolAddress((void**)&sft, d_cshift);

    prep_kernel<<<64, 256>>>(up_w, up_b, bn_g, bn_b, bn_m, bn_v);

    for (int p = 0; p < 4; p++) {
        ALConv al; al.in = x; al.py = p >> 1; al.px = p & 1;
        StConv st; st.out = bX; st.scale = scl; st.shift = sft; st.py = p >> 1; st.px = p & 1;
        gemm_k<<<dim3(392, 2), 128>>>(al, st, wc + (size_t)p * 96 * 768, 96, 768);
    }

    for (int i = 0; i < 2; i++) {
        int sh = i ? 3 : 0;
        ln_part_kernel<<<25088, 128>>>(bX, bW, n1g + i * 96, n1b + i * 96, sh);

        { ALDirect al; al.A = bW; al.K = 96;
          StQKV st; st.out = bQ; st.bias = qkvb + i * 288;
          gemm_k<<<dim3(1568, 5), 128>>>(al, st, qkvw + (size_t)i * 288 * 96, 288, 96); }

        attn_kernel<<<dim3(2048, 6), 64>>>(bQ, rel + (size_t)i * 169 * 6, bA, sh);

        { ALDirect al; al.A = bA; al.K = 96;
          StProj st; st.out = bX; st.bias = projb + i * 96; st.shift = sh;
          gemm_k<<<dim3(1568, 2), 128>>>(al, st, projw + (size_t)i * 96 * 96, 96, 96); }

        ln_plain_kernel<<<25088, 128>>>(bX, bW, n2g + i * 96, n2b + i * 96);

        { ALDirect al; al.A = bW; al.K = 96;
          StGelu st; st.out = bH; st.bias = f1b + i * HID;
          gemm_k<<<dim3(1568, 6), 128>>>(al, st, f1w + (size_t)i * HID * 96, HID, 96); }

        { ALDirect al; al.A = bH; al.K = HID;
          StFC2 st; st.out = bX; st.bias = f2b + i * 96;
          gemm_k<<<dim3(1568, 2), 128>>>(al, st, f2w + (size_t)i * 96 * HID, 96, HID); }
    }

    { ALDirect al; al.A = bX; al.K = 96;
      StOut st; st.out = out; st.bias = outb;
      gemm_k<<<dim3(1568, 1), 128>>>(al, st, outw, 48, 96); }
}

// round 4
// speedup vs baseline: 1.3625x; 1.3625x over previous
#include <cuda_runtime.h>
#include <cuda_bf16.h>
#include <math.h>
#include <stdint.h>

#define CB 8
#define C2 96
#define H2 112
#define LTOK 12544
#define NWB 2048
#define HID 384

__device__ float d_bufX[CB*LTOK*C2];
__device__ float d_bufW[CB*LTOK*C2];
__device__ float d_bufA[CB*LTOK*C2];
__device__ float d_bufQ[NWB*3*6*49*16];
__device__ float d_bufH[CB*LTOK*HID];
__device__ float d_wc[4*96*768];
__device__ float d_cscale[96];
__device__ float d_cshift[96];

// ---------------- helpers ----------------
__device__ __forceinline__ uint32_t smem_u32(const void* p) {
    uint32_t a;
    asm("{ .reg .u64 t; cvta.to.shared.u64 t, %1; cvt.u32.u64 %0, t; }" : "=r"(a) : "l"(p));
    return a;
}
__device__ __forceinline__ void ldm_x4(uint32_t* r, uint32_t addr) {
    asm volatile("ldmatrix.sync.aligned.m8n8.x4.shared.b16 {%0,%1,%2,%3}, [%4];"
        : "=r"(r[0]), "=r"(r[1]), "=r"(r[2]), "=r"(r[3]) : "r"(addr));
}
__device__ __forceinline__ void ldm_x2(uint32_t* r, uint32_t addr) {
    asm volatile("ldmatrix.sync.aligned.m8n8.x2.shared.b16 {%0,%1}, [%2];"
        : "=r"(r[0]), "=r"(r[1]) : "r"(addr));
}
__device__ __forceinline__ void mma_bf16(float* c, const uint32_t* a, const uint32_t* b) {
    asm volatile("mma.sync.aligned.m16n8k16.row.col.f32.bf16.bf16.f32 "
        "{%0,%1,%2,%3}, {%4,%5,%6,%7}, {%8,%9}, {%0,%1,%2,%3};"
        : "+f"(c[0]), "+f"(c[1]), "+f"(c[2]), "+f"(c[3])
        : "r"(a[0]), "r"(a[1]), "r"(a[2]), "r"(a[3]), "r"(b[0]), "r"(b[1]));
}
__device__ __forceinline__ void split2(float x, float y, uint32_t& h, uint32_t& l) {
    __nv_bfloat16 hx = __float2bfloat16_rn(x), hy = __float2bfloat16_rn(y);
    float rx = x - __bfloat162float(hx), ry = y - __bfloat162float(hy);
    __nv_bfloat16 lx = __float2bfloat16_rn(rx), ly = __float2bfloat16_rn(ry);
    h = ((uint32_t)__bfloat16_as_ushort(hy) << 16) | (uint32_t)__bfloat16_as_ushort(hx);
    l = ((uint32_t)__bfloat16_as_ushort(ly) << 16) | (uint32_t)__bfloat16_as_ushort(lx);
}
__device__ __forceinline__ void split8(float4 a, float4 b, uint4& hv, uint4& lv) {
    split2(a.x, a.y, hv.x, lv.x);
    split2(a.z, a.w, hv.y, lv.y);
    split2(b.x, b.y, hv.z, lv.z);
    split2(b.z, b.w, hv.w, lv.w);
}

// ---------------- prep: parity-combined conv weights -------------------------
__global__ void prep_kernel(const float* __restrict__ up_w, const float* __restrict__ up_b,
                            const float* __restrict__ bn_g, const float* __restrict__ bn_b,
                            const float* __restrict__ bn_m, const float* __restrict__ bn_v) {
    int tid = blockIdx.x * blockDim.x + threadIdx.x;
    if (tid < 96) {
        float s = bn_g[tid] * rsqrtf(bn_v[tid] + 1e-5f);
        d_cscale[tid] = s;
        d_cshift[tid] = (up_b[tid] - bn_m[tid]) * s + bn_b[tid];
    }
    int total = 4 * 96 * 192;
    for (int idx = tid; idx < total; idx += gridDim.x * blockDim.x) {
        int p  = idx / (96 * 192);
        int r  = idx % (96 * 192);
        int co = r / 192, ci = r % 192;
        int py = p >> 1, px = p & 1;
        const float* w = up_w + ((size_t)co * 192 + ci) * 9;
        float cs[3][2];
        #pragma unroll
        for (int ky = 0; ky < 3; ky++) {
            float w0 = w[ky*3], w1 = w[ky*3+1], w2 = w[ky*3+2];
            cs[ky][0] = (px == 0) ? w0 : (w0 + w1);
            cs[ky][1] = (px == 0) ? (w1 + w2) : w2;
        }
        float* dst = d_wc + ((size_t)p * 96 + co) * 768 + ci * 4;
        #pragma unroll
        for (int b2 = 0; b2 < 2; b2++) {
            dst[b2]     = (py == 0) ? cs[0][b2] : (cs[0][b2] + cs[1][b2]);
            dst[2 + b2] = (py == 0) ? (cs[1][b2] + cs[2][b2]) : cs[2][b2];
        }
    }
}

// ---------------- A loaders --------------------------------------------------
struct ALDirect {
    const float* A; int K;
    struct Ctx { const float* p; };
    __device__ Ctx prep(int m) const { Ctx c; c.p = A + (size_t)m * K; return c; }
    __device__ float4 load(const Ctx& c, int k) const { return *(const float4*)(c.p + k); }
};
struct ALConv {
    const float* in; int py, px;
    struct Ctx { const float* base; int o0, o1, o2, o3; };
    __device__ Ctx prep(int m) const {
        int b = m / 3136, r = m - b * 3136;
        int ty = r / 56, tx = r - ty * 56;
        int r0 = ty - 1 + py, r1 = r0 + 1;
        int c0 = tx - 1 + px, c1 = c0 + 1;
        bool r0v = (unsigned)r0 < 56u, r1v = (unsigned)r1 < 56u;
        bool c0v = (unsigned)c0 < 56u, c1v = (unsigned)c1 < 56u;
        Ctx c;
        c.base = in + (size_t)b * 192 * 3136;
        c.o0 = (r0v && c0v) ? r0 * 56 + c0 : -1;
        c.o1 = (r0v && c1v) ? r0 * 56 + c1 : -1;
        c.o2 = (r1v && c0v) ? r1 * 56 + c0 : -1;
        c.o3 = (r1v && c1v) ? r1 * 56 + c1 : -1;
        return c;
    }
    __device__ float4 load(const Ctx& c, int k) const {
        const float* p = c.base + (size_t)(k >> 2) * 3136;
        float4 v;
        v.x = (c.o0 >= 0) ? p[c.o0] : 0.f;
        v.y = (c.o1 >= 0) ? p[c.o1] : 0.f;
        v.z = (c.o2 >= 0) ? p[c.o2] : 0.f;
        v.w = (c.o3 >= 0) ? p[c.o3] : 0.f;
        return v;
    }
};

// ---------------- epilogues --------------------------------------------------
struct StConv {
    float* out; const float* scale; const float* shift; int py, px;
    __device__ void store(int m, int n, float v) const {
        v = fmaxf(v * scale[n] + shift[n], 0.f);
        int b = m / 3136, r = m - b * 3136;
        int ty = r / 56, tx = r - ty * 56;
        int y = 2 * ty + py, x = 2 * tx + px;
        out[((size_t)b * LTOK + y * H2 + x) * C2 + n] = v;
    }
};
struct StQKV {
    float* out; const float* bias;
    __device__ void store(int m, int n, float v) const {
        v += bias[n];
        int s3 = n / 96, rem = n - s3 * 96;
        int h = rem >> 4, d = rem & 15;
        if (s3 == 0) v *= 0.25f;
        int bw = m / 49, nn = m - bw * 49;
        out[(((size_t)(bw * 3 + s3) * 6 + h) * 49 + nn) * 16 + d] = v;
    }
};
struct StProj {
    float* out; const float* bias; int shift;
    __device__ void store(int m, int n, float v) const {
        int bw = m / 49, nn = m - bw * 49;
        int b = bw >> 8, wy = (bw >> 4) & 15, wx = bw & 15;
        int iy = nn / 7, ix = nn - iy * 7;
        int y = wy * 7 + iy + shift; if (y >= H2) y -= H2;
        int x = wx * 7 + ix + shift; if (x >= H2) x -= H2;
        out[((size_t)b * LTOK + y * H2 + x) * C2 + n] += v + bias[n];
    }
};
struct StGelu {
    float* out; const float* bias;
    __device__ void store(int m, int n, float v) const {
        v += bias[n];
        v = 0.5f * v * (1.0f + erff(v * 0.70710678118654752f));
        out[(size_t)m * HID + n] = v;
    }
};
struct StFC2 {
    float* out; const float* bias;
    __device__ void store(int m, int n, float v) const {
        out[(size_t)m * C2 + n] += v + bias[n];
    }
};
struct StOut {
    float* out; const float* bias;
    __device__ void store(int m, int n, float v) const {
        v = fmaxf(v + bias[n], 0.f);
        int b = m / LTOK, pix = m - b * LTOK;
        out[((size_t)b * 48 + n) * LTOK + pix] = v;
    }
};

// ---------------- HMMA GEMM: 128x64 tile, 8 warps, bf16 hi/lo 3-pass ---------
// smem rows padded to 40 bf16 (80B) -> conflict-free ldmatrix.
#define SROW 40

template<class AL, class ST>
__global__ void __launch_bounds__(256) mma_gemm(AL al, ST st, const float* __restrict__ Bw,
                                                int Nt, int K) {
    __shared__ __align__(16) uint16_t sAh[128 * SROW];
    __shared__ __align__(16) uint16_t sAl[128 * SROW];
    __shared__ __align__(16) uint16_t sBh[64 * SROW];
    __shared__ __align__(16) uint16_t sBl[64 * SROW];

    const int tid  = threadIdx.x;
    const int wid  = tid >> 5, lane = tid & 31;
    const int wm   = wid & 3, wn = wid >> 2;     // 4 x 2 warp grid
    const int m0   = blockIdx.x << 7;
    const int n0   = blockIdx.y << 6;

    // loader assignments
    const int arow  = tid & 127;
    const int akoff = (tid >> 7) << 4;           // 0 or 16
    typename AL::Ctx ctx = al.prep(m0 + arow);
    const int brow  = tid & 63;
    const int bkoff = ((tid >> 6) & 1) << 4;
    const bool bldr = (tid < 128);
    const float* bp = (bldr && (n0 + brow) < Nt) ? (Bw + (size_t)(n0 + brow) * K) : (const float*)0;

    const uint32_t uAh = smem_u32(sAh), uAl = smem_u32(sAl);
    const uint32_t uBh = smem_u32(sBh), uBl = smem_u32(sBl);

    float acc[2][4][4];
    #pragma unroll
    for (int mi = 0; mi < 2; mi++)
        #pragma unroll
        for (int ni = 0; ni < 4; ni++)
            #pragma unroll
            for (int r = 0; r < 4; r++) acc[mi][ni][r] = 0.f;

    // fragment address bases (bytes)
    const uint32_t aAddrOff = (uint32_t)((wm * 32 + (lane & 15)) * SROW + (lane >> 4) * 8) * 2;
    const uint32_t bAddrOff = (uint32_t)((wn * 32 + (lane & 7)) * SROW + ((lane >> 3) & 1) * 8) * 2;

    const int nchunks = K >> 5;                  // K divisible by 32
    for (int kc = 0; kc < nchunks; kc++) {
        // load A: 16 floats per thread
        {
            int kb = (kc << 5) + akoff;
            float4 a0 = al.load(ctx, kb), a1 = al.load(ctx, kb + 4);
            float4 a2 = al.load(ctx, kb + 8), a3 = al.load(ctx, kb + 12);
            uint4 h0, l0, h1, l1;
            split8(a0, a1, h0, l0);
            split8(a2, a3, h1, l1);
            uint16_t* dh = sAh + arow * SROW + akoff;
            uint16_t* dl = sAl + arow * SROW + akoff;
            *(uint4*)dh = h0; *(uint4*)(dh + 8) = h1;
            *(uint4*)dl = l0; *(uint4*)(dl + 8) = l1;
        }
        // load B: 16 floats per thread (first 128 threads)
        if (bldr) {
            int kb = (kc << 5) + bkoff;
            float4 b0 = make_float4(0,0,0,0), b1 = b0, b2 = b0, b3 = b0;
            if (bp) {
                b0 = *(const float4*)(bp + kb);     b1 = *(const float4*)(bp + kb + 4);
                b2 = *(const float4*)(bp + kb + 8); b3 = *(const float4*)(bp + kb + 12);
            }
            uint4 h0, l0, h1, l1;
            split8(b0, b1, h0, l0);
            split8(b2, b3, h1, l1);
            uint16_t* dh = sBh + brow * SROW + bkoff;
            uint16_t* dl = sBl + brow * SROW + bkoff;
            *(uint4*)dh = h0; *(uint4*)(dh + 8) = h1;
            *(uint4*)dl = l0; *(uint4*)(dl + 8) = l1;
        }
        __syncthreads();

        #pragma unroll
        for (int ks = 0; ks < 32; ks += 16) {
            uint32_t Ah[2][4], Al[2][4];
            ldm_x4(Ah[0], uAh + aAddrOff + ks * 2);
            ldm_x4(Ah[1], uAh + aAddrOff + (16 * SROW + ks) * 2);
            ldm_x4(Al[0], uAl + aAddrOff + ks * 2);
            ldm_x4(Al[1], uAl + aAddrOff + (16 * SROW + ks) * 2);
            #pragma unroll
            for (int ni = 0; ni < 4; ni++) {
                uint32_t b[2];
                ldm_x2(b, uBh + bAddrOff + (ni * 8 * SROW + ks) * 2);
                mma_bf16(acc[0][ni], Ah[0], b);
                mma_bf16(acc[1][ni], Ah[1], b);
                mma_bf16(acc[0][ni], Al[0], b);
                mma_bf16(acc[1][ni], Al[1], b);
                uint32_t bl[2];
                ldm_x2(bl, uBl + bAddrOff + (ni * 8 * SROW + ks) * 2);
                mma_bf16(acc[0][ni], Ah[0], bl);
                mma_bf16(acc[1][ni], Ah[1], bl);
            }
        }
        __syncthreads();
    }

    // epilogue
    #pragma unroll
    for (int mi = 0; mi < 2; mi++) {
        #pragma unroll
        for (int ni = 0; ni < 4; ni++) {
            #pragma unroll
            for (int r = 0; r < 4; r++) {
                int m = m0 + wm * 32 + mi * 16 + (lane >> 2) + ((r >> 1) << 3);
                int n = n0 + wn * 32 + ni * 8 + ((lane & 3) << 1) + (r & 1);
                if (n < Nt) st.store(m, n, acc[mi][ni][r]);
            }
        }
    }
}

// ---------------- LayerNorm --------------------------------------------------
__device__ __forceinline__ float warp_sum(float v) {
    #pragma unroll
    for (int o = 16; o; o >>= 1) v += __shfl_xor_sync(0xffffffffu, v, o);
    return v;
}
__global__ void __launch_bounds__(128) ln_part_kernel(const float* __restrict__ src,
                                                      float* __restrict__ dst,
                                                      const float* __restrict__ gg,
                                                      const float* __restrict__ be,
                                                      int shift) {
    int warp = threadIdx.x >> 5, lane = threadIdx.x & 31;
    int gidx = blockIdx.x * 4 + warp;
    int bw = gidx / 49, nn = gidx - bw * 49;
    int b = bw >> 8, wy = (bw >> 4) & 15, wx = bw & 15;
    int iy = nn / 7, ix = nn - iy * 7;
    int ys = wy * 7 + iy + shift; if (ys >= H2) ys -= H2;
    int xs = wx * 7 + ix + shift; if (xs >= H2) xs -= H2;
    const float* sp = src + ((size_t)b * LTOK + ys * H2 + xs) * C2;
    float v0 = sp[lane], v1 = sp[lane + 32], v2 = sp[lane + 64];
    float mean = warp_sum(v0 + v1 + v2) * (1.f / 96.f);
    float d0 = v0 - mean, d1 = v1 - mean, d2 = v2 - mean;
    float var = warp_sum(d0*d0 + d1*d1 + d2*d2) * (1.f / 96.f);
    float inv = rsqrtf(var + 1e-5f);
    float* dp = dst + (size_t)gidx * C2;
    dp[lane]      = d0 * inv * gg[lane]      + be[lane];
    dp[lane + 32] = d1 * inv * gg[lane + 32] + be[lane + 32];
    dp[lane + 64] = d2 * inv * gg[lane + 64] + be[lane + 64];
}
__global__ void __launch_bounds__(128) ln_plain_kernel(const float* __restrict__ src,
                                                       float* __restrict__ dst,
                                                       const float* __restrict__ gg,
                                                       const float* __restrict__ be) {
    int warp = threadIdx.x >> 5, lane = threadIdx.x & 31;
    size_t gidx = (size_t)blockIdx.x * 4 + warp;
    const float* sp = src + gidx * C2;
    float v0 = sp[lane], v1 = sp[lane + 32], v2 = sp[lane + 64];
    float mean = warp_sum(v0 + v1 + v2) * (1.f / 96.f);
    float d0 = v0 - mean, d1 = v1 - mean, d2 = v2 - mean;
    float var = warp_sum(d0*d0 + d1*d1 + d2*d2) * (1.f / 96.f);
    float inv = rsqrtf(var + 1e-5f);
    float* dp = dst + gidx * C2;
    dp[lane]      = d0 * inv * gg[lane]      + be[lane];
    dp[lane + 32] = d1 * inv * gg[lane + 32] + be[lane + 32];
    dp[lane + 64] = d2 * inv * gg[lane + 64] + be[lane + 64];
}

// ---------------- window attention -------------------------------------------
__global__ void __launch_bounds__(64) attn_kernel(const float* __restrict__ qkv,
                                                  const float* __restrict__ rel,
                                                  float* __restrict__ outA,
                                                  int shifted) {
    __shared__ float sq[784], sk[784], sv[784], srel[169];
    __shared__ float sp[49 * 49];
    __shared__ int slbl[49];
    int bw = blockIdx.x, h = blockIdx.y;
    int tid = threadIdx.x;
    const float* qb = qkv + ((size_t)(bw * 3 + 0) * 6 + h) * 784;
    const float* kb = qkv + ((size_t)(bw * 3 + 1) * 6 + h) * 784;
    const float* vb = qkv + ((size_t)(bw * 3 + 2) * 6 + h) * 784;
    for (int i = tid; i < 784; i += 64) { sq[i] = qb[i]; sk[i] = kb[i]; sv[i] = vb[i]; }
    for (int i = tid; i < 169; i += 64) srel[i] = rel[i * 6 + h];
    if (tid < 49) {
        if (shifted) {
            int wy = (bw >> 4) & 15, wx = bw & 15;
            int yy = wy * 7 + tid / 7, xx = wx * 7 + tid % 7;
            int ry = (yy < 105) ? 0 : ((yy < 109) ? 1 : 2);
            int rx = (xx < 105) ? 0 : ((xx < 109) ? 1 : 2);
            slbl[tid] = ry * 3 + rx;
        } else slbl[tid] = 0;
    }
    __syncthreads();
    if (tid < 49) {
        int iy = tid / 7, ix = tid - iy * 7;
        float4 q0 = *(const float4*)&sq[tid*16+0];
        float4 q1 = *(const float4*)&sq[tid*16+4];
        float4 q2 = *(const float4*)&sq[tid*16+8];
        float4 q3 = *(const float4*)&sq[tid*16+12];
        int mylbl = slbl[tid];
        float mx = -1e30f;
        int jy = 0, jx = 0;
        for (int m = 0; m < 49; m++) {
            float4 k0 = *(const float4*)&sk[m*16+0];
            float4 k1 = *(const float4*)&sk[m*16+4];
            float4 k2 = *(const float4*)&sk[m*16+8];
            float4 k3 = *(const float4*)&sk[m*16+12];
            float d = q0.x*k0.x+q0.y*k0.y+q0.z*k0.z+q0.w*k0.w
                    + q1.x*k1.x+q1.y*k1.y+q1.z*k1.z+q1.w*k1.w
                    + q2.x*k2.x+q2.y*k2.y+q2.z*k2.z+q2.w*k2.w
                    + q3.x*k3.x+q3.y*k3.y+q3.z*k3.z+q3.w*k3.w;
            d += srel[(iy - jy + 6) * 13 + (ix - jx + 6)];
            if (shifted && slbl[m] != mylbl) d -= 100.f;
            sp[tid * 49 + m] = d;
            mx = fmaxf(mx, d);
            if (++jx == 7) { jx = 0; ++jy; }
        }
        float sum = 0.f;
        for (int m = 0; m < 49; m++) {
            float e = __expf(sp[tid * 49 + m] - mx);
            sp[tid * 49 + m] = e;
            sum += e;
        }
        float inv = 1.f / sum;
        float o[16];
        #pragma unroll
        for (int d = 0; d < 16; d++) o[d] = 0.f;
        for (int m = 0; m < 49; m++) {
            float p = sp[tid * 49 + m] * inv;
            float4 v0 = *(const float4*)&sv[m*16+0];
            float4 v1 = *(const float4*)&sv[m*16+4];
            float4 v2 = *(const float4*)&sv[m*16+8];
            float4 v3 = *(const float4*)&sv[m*16+12];
            o[0]+=p*v0.x; o[1]+=p*v0.y; o[2]+=p*v0.z; o[3]+=p*v0.w;
            o[4]+=p*v1.x; o[5]+=p*v1.y; o[6]+=p*v1.z; o[7]+=p*v1.w;
            o[8]+=p*v2.x; o[9]+=p*v2.y; o[10]+=p*v2.z; o[11]+=p*v2.w;
            o[12]+=p*v3.x; o[13]+=p*v3.y; o[14]+=p*v3.z; o[15]+=p*v3.w;
        }
        float* op = outA + ((size_t)bw * 49 + tid) * C2 + h * 16;
        *(float4*)(op+0)  = make_float4(o[0],o[1],o[2],o[3]);
        *(float4*)(op+4)  = make_float4(o[4],o[5],o[6],o[7]);
        *(float4*)(op+8)  = make_float4(o[8],o[9],o[10],o[11]);
        *(float4*)(op+12) = make_float4(o[12],o[13],o[14],o[15]);
    }
}

// ---------------- launch -----------------------------------------------------
extern "C" void kernel_launch(void* const* d_in, const int* in_sizes, int n_in,
                              void* d_out, int out_size) {
    (void)in_sizes; (void)n_in; (void)out_size;
    const float* x     = (const float*)d_in[0];
    const float* up_w  = (const float*)d_in[1];
    const float* up_b  = (const float*)d_in[2];
    const float* bn_g  = (const float*)d_in[3];
    const float* bn_b  = (const float*)d_in[4];
    const float* bn_m  = (const float*)d_in[5];
    const float* bn_v  = (const float*)d_in[6];
    const float* n1g   = (const float*)d_in[7];
    const float* n1b   = (const float*)d_in[8];
    const float* qkvw  = (const float*)d_in[9];
    const float* qkvb  = (const float*)d_in[10];
    const float* projw = (const float*)d_in[11];
    const float* projb = (const float*)d_in[12];
    const float* rel   = (const float*)d_in[13];
    const float* n2g   = (const float*)d_in[14];
    const float* n2b   = (const float*)d_in[15];
    const float* f1w   = (const float*)d_in[16];
    const float* f1b   = (const float*)d_in[17];
    const float* f2w   = (const float*)d_in[18];
    const float* f2b   = (const float*)d_in[19];
    const float* outw  = (const float*)d_in[20];
    const float* outb  = (const float*)d_in[21];
    float* out = (float*)d_out;

    float *bX, *bW, *bA, *bQ, *bH, *wc, *scl, *sft;
    cudaGetSymbolAddress((void**)&bX,  d_bufX);
    cudaGetSymbolAddress((void**)&bW,  d_bufW);
    cudaGetSymbolAddress((void**)&bA,  d_bufA);
    cudaGetSymbolAddress((void**)&bQ,  d_bufQ);
    cudaGetSymbolAddress((void**)&bH,  d_bufH);
    cudaGetSymbolAddress((void**)&wc,  d_wc);
    cudaGetSymbolAddress((void**)&scl, d_cscale);
    cudaGetSymbolAddress((void**)&sft, d_cshift);

    prep_kernel<<<64, 256>>>(up_w, up_b, bn_g, bn_b, bn_m, bn_v);

    for (int p = 0; p < 4; p++) {
        ALConv al; al.in = x; al.py = p >> 1; al.px = p & 1;
        StConv st; st.out = bX; st.scale = scl; st.shift = sft; st.py = p >> 1; st.px = p & 1;
        mma_gemm<<<dim3(196, 2), 256>>>(al, st, wc + (size_t)p * 96 * 768, 96, 768);
    }

    for (int i = 0; i < 2; i++) {
        int sh = i ? 3 : 0;
        ln_part_kernel<<<25088, 128>>>(bX, bW, n1g + i * 96, n1b + i * 96, sh);

        { ALDirect al; al.A = bW; al.K = 96;
          StQKV st; st.out = bQ; st.bias = qkvb + i * 288;
          mma_gemm<<<dim3(784, 5), 256>>>(al, st, qkvw + (size_t)i * 288 * 96, 288, 96); }

        attn_kernel<<<dim3(2048, 6), 64>>>(bQ, rel + (size_t)i * 169 * 6, bA, sh);

        { ALDirect al; al.A = bA; al.K = 96;
          StProj st; st.out = bX; st.bias = projb + i * 96; st.shift = sh;
          mma_gemm<<<dim3(784, 2), 256>>>(al, st, projw + (size_t)i * 96 * 96, 96, 96); }

        ln_plain_kernel<<<25088, 128>>>(bX, bW, n2g + i * 96, n2b + i * 96);

        { ALDirect al; al.A = bW; al.K = 96;
          StGelu st; st.out = bH; st.bias = f1b + i * HID;
          mma_gemm<<<dim3(784, 6), 256>>>(al, st, f1w + (size_t)i * HID * 96, HID, 96); }

        { ALDirect al; al.A = bH; al.K = HID;
          StFC2 st; st.out = bX; st.bias = f2b + i * 96;
          mma_gemm<<<dim3(784, 2), 256>>>(al, st, f2w + (size_t)i * 96 * HID, 96, 384); }
    }

    { ALDirect al; al.A = bX; al.K = 96;
      StOut st; st.out = out; st.bias = outb;
      mma_gemm<<<dim3(784, 1), 256>>>(al, st, outw, 48, 96); }
}

// round 5
// speedup vs baseline: 1.5004x; 1.1012x over previous
#include <cuda_runtime.h>
#include <cuda_bf16.h>
#include <math.h>
#include <stdint.h>

#define CB 8
#define C2 96
#define H2 112
#define LTOK 12544
#define NWB 2048
#define HID 384
#define SROW 104              // smem row pitch in halves (conflict-free ldmatrix)
#define A_HALVES (128 * SROW)
#define B_HALVES (96 * SROW)
#define SMEM_BYTES ((2 * A_HALVES + 2 * B_HALVES) * 2)

__device__ float d_bufX[CB*LTOK*C2];
__device__ float d_bufW[CB*LTOK*C2];
__device__ float d_bufA[CB*LTOK*C2];
__device__ float d_bufQ[NWB*3*6*49*16];
__device__ float d_bufH[CB*LTOK*HID];
__device__ float d_wc[4*96*768];
__device__ float d_cscale[96];
__device__ float d_cshift[96];

// ---------------- helpers ----------------
__device__ __forceinline__ uint32_t smem_u32(const void* p) {
    uint32_t a;
    asm("{ .reg .u64 t; cvta.to.shared.u64 t, %1; cvt.u32.u64 %0, t; }" : "=r"(a) : "l"(p));
    return a;
}
__device__ __forceinline__ void ldm_x4(uint32_t* r, uint32_t addr) {
    asm volatile("ldmatrix.sync.aligned.m8n8.x4.shared.b16 {%0,%1,%2,%3}, [%4];"
        : "=r"(r[0]), "=r"(r[1]), "=r"(r[2]), "=r"(r[3]) : "r"(addr));
}
__device__ __forceinline__ void ldm_x2(uint32_t* r, uint32_t addr) {
    asm volatile("ldmatrix.sync.aligned.m8n8.x2.shared.b16 {%0,%1}, [%2];"
        : "=r"(r[0]), "=r"(r[1]) : "r"(addr));
}
__device__ __forceinline__ void mma_bf16(float* c, const uint32_t* a, const uint32_t* b) {
    asm volatile("mma.sync.aligned.m16n8k16.row.col.f32.bf16.bf16.f32 "
        "{%0,%1,%2,%3}, {%4,%5,%6,%7}, {%8,%9}, {%0,%1,%2,%3};"
        : "+f"(c[0]), "+f"(c[1]), "+f"(c[2]), "+f"(c[3])
        : "r"(a[0]), "r"(a[1]), "r"(a[2]), "r"(a[3]), "r"(b[0]), "r"(b[1]));
}
__device__ __forceinline__ void split2(float x, float y, uint32_t& h, uint32_t& l) {
    __nv_bfloat16 hx = __float2bfloat16_rn(x), hy = __float2bfloat16_rn(y);
    float rx = x - __bfloat162float(hx), ry = y - __bfloat162float(hy);
    __nv_bfloat16 lx = __float2bfloat16_rn(rx), ly = __float2bfloat16_rn(ry);
    h = ((uint32_t)__bfloat16_as_ushort(hy) << 16) | (uint32_t)__bfloat16_as_ushort(hx);
    l = ((uint32_t)__bfloat16_as_ushort(ly) << 16) | (uint32_t)__bfloat16_as_ushort(lx);
}
__device__ __forceinline__ void split4(float4 a, uint2& h, uint2& l) {
    split2(a.x, a.y, h.x, l.x);
    split2(a.z, a.w, h.y, l.y);
}

// ---------------- prep: parity-combined conv weights -------------------------
__global__ void prep_kernel(const float* __restrict__ up_w, const float* __restrict__ up_b,
                            const float* __restrict__ bn_g, const float* __restrict__ bn_b,
                            const float* __restrict__ bn_m, const float* __restrict__ bn_v) {
    int tid = blockIdx.x * blockDim.x + threadIdx.x;
    if (tid < 96) {
        float s = bn_g[tid] * rsqrtf(bn_v[tid] + 1e-5f);
        d_cscale[tid] = s;
        d_cshift[tid] = (up_b[tid] - bn_m[tid]) * s + bn_b[tid];
    }
    int total = 4 * 96 * 192;
    for (int idx = tid; idx < total; idx += gridDim.x * blockDim.x) {
        int p  = idx / (96 * 192);
        int r  = idx % (96 * 192);
        int co = r / 192, ci = r % 192;
        int py = p >> 1, px = p & 1;
        const float* w = up_w + ((size_t)co * 192 + ci) * 9;
        float cs[3][2];
        #pragma unroll
        for (int ky = 0; ky < 3; ky++) {
            float w0 = w[ky*3], w1 = w[ky*3+1], w2 = w[ky*3+2];
            cs[ky][0] = (px == 0) ? w0 : (w0 + w1);
            cs[ky][1] = (px == 0) ? (w1 + w2) : w2;
        }
        float* dst = d_wc + ((size_t)p * 96 + co) * 768 + ci * 4;
        #pragma unroll
        for (int b2 = 0; b2 < 2; b2++) {
            dst[b2]     = (py == 0) ? cs[0][b2] : (cs[0][b2] + cs[1][b2]);
            dst[2 + b2] = (py == 0) ? (cs[1][b2] + cs[2][b2]) : cs[2][b2];
        }
    }
}

// ---------------- A loaders --------------------------------------------------
struct ALDirect {
    const float* A; int K;
    struct Ctx { const float* p; };
    __device__ Ctx prep(int m) const { Ctx c; c.p = A + (size_t)m * K; return c; }
    __device__ float4 load(const Ctx& c, int k) const { return *(const float4*)(c.p + k); }
};
struct ALConv {
    const float* in; int py, px;
    struct Ctx { const float* base; int o0, o1, o2, o3; };
    __device__ Ctx prep(int m) const {
        int b = m / 3136, r = m - b * 3136;
        int ty = r / 56, tx = r - ty * 56;
        int r0 = ty - 1 + py, r1 = r0 + 1;
        int c0 = tx - 1 + px, c1 = c0 + 1;
        bool r0v = (unsigned)r0 < 56u, r1v = (unsigned)r1 < 56u;
        bool c0v = (unsigned)c0 < 56u, c1v = (unsigned)c1 < 56u;
        Ctx c;
        c.base = in + (size_t)b * 192 * 3136;
        c.o0 = (r0v && c0v) ? r0 * 56 + c0 : -1;
        c.o1 = (r0v && c1v) ? r0 * 56 + c1 : -1;
        c.o2 = (r1v && c0v) ? r1 * 56 + c0 : -1;
        c.o3 = (r1v && c1v) ? r1 * 56 + c1 : -1;
        return c;
    }
    __device__ float4 load(const Ctx& c, int k) const {
        const float* p = c.base + (size_t)(k >> 2) * 3136;
        float4 v;
        v.x = (c.o0 >= 0) ? p[c.o0] : 0.f;
        v.y = (c.o1 >= 0) ? p[c.o1] : 0.f;
        v.z = (c.o2 >= 0) ? p[c.o2] : 0.f;
        v.w = (c.o3 >= 0) ? p[c.o3] : 0.f;
        return v;
    }
};

// ---------------- epilogues --------------------------------------------------
struct StConv {
    float* out; const float* scale; const float* shift; int py, px;
    __device__ void store(int m, int n, float v) const {
        v = fmaxf(v * scale[n] + shift[n], 0.f);
        int b = m / 3136, r = m - b * 3136;
        int ty = r / 56, tx = r - ty * 56;
        int y = 2 * ty + py, x = 2 * tx + px;
        out[((size_t)b * LTOK + y * H2 + x) * C2 + n] = v;
    }
};
struct StQKV {
    float* out; const float* bias;
    __device__ void store(int m, int n, float v) const {
        v += bias[n];
        int s3 = n / 96, rem = n - s3 * 96;
        int h = rem >> 4, d = rem & 15;
        if (s3 == 0) v *= 0.25f;
        int bw = m / 49, nn = m - bw * 49;
        out[(((size_t)(bw * 3 + s3) * 6 + h) * 49 + nn) * 16 + d] = v;
    }
};
struct StProj {
    float* out; const float* bias; int shift;
    __device__ void store(int m, int n, float v) const {
        int bw = m / 49, nn = m - bw * 49;
        int b = bw >> 8, wy = (bw >> 4) & 15, wx = bw & 15;
        int iy = nn / 7, ix = nn - iy * 7;
        int y = wy * 7 + iy + shift; if (y >= H2) y -= H2;
        int x = wx * 7 + ix + shift; if (x >= H2) x -= H2;
        out[((size_t)b * LTOK + y * H2 + x) * C2 + n] += v + bias[n];
    }
};
struct StGelu {
    float* out; const float* bias;
    __device__ void store(int m, int n, float v) const {
        v += bias[n];
        v = 0.5f * v * (1.0f + erff(v * 0.70710678118654752f));
        out[(size_t)m * HID + n] = v;
    }
};
struct StFC2 {
    float* out; const float* bias;
    __device__ void store(int m, int n, float v) const {
        out[(size_t)m * C2 + n] += v + bias[n];
    }
};
struct StOut {
    float* out; const float* bias;
    __device__ void store(int m, int n, float v) const {
        v = fmaxf(v + bias[n], 0.f);
        int b = m / LTOK, pix = m - b * LTOK;
        out[((size_t)b * 48 + n) * LTOK + pix] = v;
    }
};

// ---------------- HMMA GEMM: 128x96 tile, 8 warps (4x2), K-stage 96 ----------
template<class AL, class ST>
__global__ void __launch_bounds__(256) mma_gemm(AL al, ST st, const float* __restrict__ Bw,
                                                int Nt, int K) {
    extern __shared__ uint16_t sm[];
    uint16_t* sAh = sm;
    uint16_t* sAl = sm + A_HALVES;
    uint16_t* sBh = sm + 2 * A_HALVES;
    uint16_t* sBl = sBh + B_HALVES;

    const int tid  = threadIdx.x;
    const int wid  = tid >> 5, lane = tid & 31;
    const int wm   = wid & 3, wn = wid >> 2;     // 4 x 2 warps; wn covers 48 cols
    const int m0   = blockIdx.x << 7;
    const int n0   = blockIdx.y * 96;

    // A loader: 2 threads per row, 48 cols each
    const int arow = tid & 127, ahalf = tid >> 7;
    typename AL::Ctx ctx = al.prep(m0 + arow);
    // B loader: threads < 192, 2 per row
    const bool bact = tid < 192;
    const int brow  = bact ? (tid < 96 ? tid : tid - 96) : 0;
    const int bhalf = (tid >= 96) ? 1 : 0;
    const float* bp = (bact && (n0 + brow) < Nt) ? (Bw + (size_t)(n0 + brow) * K) : (const float*)0;

    const uint32_t uAh = smem_u32(sAh), uAl = smem_u32(sAl);
    const uint32_t uBh = smem_u32(sBh), uBl = smem_u32(sBl);

    float acc[2][6][4];
    #pragma unroll
    for (int mi = 0; mi < 2; mi++)
        #pragma unroll
        for (int ni = 0; ni < 6; ni++)
            #pragma unroll
            for (int r = 0; r < 4; r++) acc[mi][ni][r] = 0.f;

    const uint32_t aoff = (uint32_t)((wm * 32 + (lane & 15)) * SROW + (lane >> 4) * 8);
    const uint32_t boff = (uint32_t)((wn * 48 + (lane & 7)) * SROW + ((lane >> 3) & 1) * 8);

    const int nchunks = K / 96;
    for (int kc = 0; kc < nchunks; kc++) {
        const int kb = kc * 96;
        if (kc > 0) __syncthreads();
        {
            uint16_t* dAh = sAh + arow * SROW + ahalf * 48;
            uint16_t* dAl = sAl + arow * SROW + ahalf * 48;
            #pragma unroll
            for (int j = 0; j < 12; j++) {
                float4 v = al.load(ctx, kb + ahalf * 48 + j * 4);
                uint2 h, l;
                split4(v, h, l);
                *(uint2*)(dAh + j * 4) = h;
                *(uint2*)(dAl + j * 4) = l;
            }
        }
        if (bact) {
            uint16_t* dBh = sBh + brow * SROW + bhalf * 48;
            uint16_t* dBl = sBl + brow * SROW + bhalf * 48;
            #pragma unroll
            for (int j = 0; j < 12; j++) {
                float4 v = make_float4(0.f, 0.f, 0.f, 0.f);
                if (bp) v = *(const float4*)(bp + kb + bhalf * 48 + j * 4);
                uint2 h, l;
                split4(v, h, l);
                *(uint2*)(dBh + j * 4) = h;
                *(uint2*)(dBl + j * 4) = l;
            }
        }
        __syncthreads();

        #pragma unroll
        for (int ks = 0; ks < 96; ks += 16) {
            uint32_t Ah[2][4], Al[2][4];
            ldm_x4(Ah[0], uAh + (aoff + ks) * 2);
            ldm_x4(Ah[1], uAh + (aoff + 16 * SROW + ks) * 2);
            ldm_x4(Al[0], uAl + (aoff + ks) * 2);
            ldm_x4(Al[1], uAl + (aoff + 16 * SROW + ks) * 2);
            #pragma unroll
            for (int ni = 0; ni < 6; ni++) {
                uint32_t bh[2], bl[2];
                ldm_x2(bh, uBh + (boff + ni * 8 * SROW + ks) * 2);
                mma_bf16(acc[0][ni], Ah[0], bh);
                mma_bf16(acc[1][ni], Ah[1], bh);
                mma_bf16(acc[0][ni], Al[0], bh);
                mma_bf16(acc[1][ni], Al[1], bh);
                ldm_x2(bl, uBl + (boff + ni * 8 * SROW + ks) * 2);
                mma_bf16(acc[0][ni], Ah[0], bl);
                mma_bf16(acc[1][ni], Ah[1], bl);
            }
        }
    }

    #pragma unroll
    for (int mi = 0; mi < 2; mi++) {
        #pragma unroll
        for (int ni = 0; ni < 6; ni++) {
            #pragma unroll
            for (int r = 0; r < 4; r++) {
                int m = m0 + wm * 32 + mi * 16 + (lane >> 2) + ((r >> 1) << 3);
                int n = n0 + wn * 48 + ni * 8 + ((lane & 3) << 1) + (r & 1);
                if (n < Nt) st.store(m, n, acc[mi][ni][r]);
            }
        }
    }
}

// ---------------- LayerNorm --------------------------------------------------
__device__ __forceinline__ float warp_sum(float v) {
    #pragma unroll
    for (int o = 16; o; o >>= 1) v += __shfl_xor_sync(0xffffffffu, v, o);
    return v;
}
__global__ void __launch_bounds__(128) ln_part_kernel(const float* __restrict__ src,
                                                      float* __restrict__ dst,
                                                      const float* __restrict__ gg,
                                                      const float* __restrict__ be,
                                                      int shift) {
    int warp = threadIdx.x >> 5, lane = threadIdx.x & 31;
    int gidx = blockIdx.x * 4 + warp;
    int bw = gidx / 49, nn = gidx - bw * 49;
    int b = bw >> 8, wy = (bw >> 4) & 15, wx = bw & 15;
    int iy = nn / 7, ix = nn - iy * 7;
    int ys = wy * 7 + iy + shift; if (ys >= H2) ys -= H2;
    int xs = wx * 7 + ix + shift; if (xs >= H2) xs -= H2;
    const float* sp = src + ((size_t)b * LTOK + ys * H2 + xs) * C2;
    float v0 = sp[lane], v1 = sp[lane + 32], v2 = sp[lane + 64];
    float mean = warp_sum(v0 + v1 + v2) * (1.f / 96.f);
    float d0 = v0 - mean, d1 = v1 - mean, d2 = v2 - mean;
    float var = warp_sum(d0*d0 + d1*d1 + d2*d2) * (1.f / 96.f);
    float inv = rsqrtf(var + 1e-5f);
    float* dp = dst + (size_t)gidx * C2;
    dp[lane]      = d0 * inv * gg[lane]      + be[lane];
    dp[lane + 32] = d1 * inv * gg[lane + 32] + be[lane + 32];
    dp[lane + 64] = d2 * inv * gg[lane + 64] + be[lane + 64];
}
__global__ void __launch_bounds__(128) ln_plain_kernel(const float* __restrict__ src,
                                                       float* __restrict__ dst,
                                                       const float* __restrict__ gg,
                                                       const float* __restrict__ be) {
    int warp = threadIdx.x >> 5, lane = threadIdx.x & 31;
    size_t gidx = (size_t)blockIdx.x * 4 + warp;
    const float* sp = src + gidx * C2;
    float v0 = sp[lane], v1 = sp[lane + 32], v2 = sp[lane + 64];
    float mean = warp_sum(v0 + v1 + v2) * (1.f / 96.f);
    float d0 = v0 - mean, d1 = v1 - mean, d2 = v2 - mean;
    float var = warp_sum(d0*d0 + d1*d1 + d2*d2) * (1.f / 96.f);
    float inv = rsqrtf(var + 1e-5f);
    float* dp = dst + gidx * C2;
    dp[lane]      = d0 * inv * gg[lane]      + be[lane];
    dp[lane + 32] = d1 * inv * gg[lane + 32] + be[lane + 32];
    dp[lane + 64] = d2 * inv * gg[lane + 64] + be[lane + 64];
}

// ---------------- window attention: block = (window, 2 heads), scores in regs
__global__ void __launch_bounds__(128) attn_kernel(const float* __restrict__ qkv,
                                                   const float* __restrict__ rel,
                                                   float* __restrict__ outA,
                                                   int shifted) {
    __shared__ float sq[2*784], sk[2*784], sv[2*784], srel[2*169];
    __shared__ int slbl[49];
    const int bw = blockIdx.x, h0 = blockIdx.y * 2;
    const int tid = threadIdx.x;

    for (int i = tid; i < 2 * 784; i += 128) {
        int hh = i / 784, idx = i - hh * 784;
        int h = h0 + hh;
        sq[i] = qkv[(((size_t)(bw * 3 + 0) * 6 + h)) * 784 + idx];
        sk[i] = qkv[(((size_t)(bw * 3 + 1) * 6 + h)) * 784 + idx];
        sv[i] = qkv[(((size_t)(bw * 3 + 2) * 6 + h)) * 784 + idx];
    }
    for (int i = tid; i < 2 * 169; i += 128) {
        int hh = i / 169, idx = i - hh * 169;
        srel[i] = rel[idx * 6 + h0 + hh];
    }
    if (tid < 49) {
        if (shifted) {
            int wy = (bw >> 4) & 15, wx = bw & 15;
            int yy = wy * 7 + tid / 7, xx = wx * 7 + tid % 7;
            int ry = (yy < 105) ? 0 : ((yy < 109) ? 1 : 2);
            int rx = (xx < 105) ? 0 : ((xx < 109) ? 1 : 2);
            slbl[tid] = ry * 3 + rx;
        } else slbl[tid] = 0;
    }
    __syncthreads();

    const int h2 = tid >> 6, n = tid & 63;
    if (n < 49) {
        const float* qh = sq + h2 * 784;
        const float* kh = sk + h2 * 784;
        const float* vh = sv + h2 * 784;
        const float* rh = srel + h2 * 169;
        const int iy = n / 7, ix = n - iy * 7;
        float4 q0 = *(const float4*)&qh[n*16+0];
        float4 q1 = *(const float4*)&qh[n*16+4];
        float4 q2 = *(const float4*)&qh[n*16+8];
        float4 q3 = *(const float4*)&qh[n*16+12];
        const int mylbl = slbl[n];
        float s[49];
        float mx = -1e30f;
        #pragma unroll
        for (int m = 0; m < 49; m++) {
            int jy = m / 7, jx = m - jy * 7;
            float4 k0 = *(const float4*)&kh[m*16+0];
            float4 k1 = *(const float4*)&kh[m*16+4];
            float4 k2 = *(const float4*)&kh[m*16+8];
            float4 k3 = *(const float4*)&kh[m*16+12];
            float d = q0.x*k0.x+q0.y*k0.y+q0.z*k0.z+q0.w*k0.w
                    + q1.x*k1.x+q1.y*k1.y+q1.z*k1.z+q1.w*k1.w
                    + q2.x*k2.x+q2.y*k2.y+q2.z*k2.z+q2.w*k2.w
                    + q3.x*k3.x+q3.y*k3.y+q3.z*k3.z+q3.w*k3.w;
            d += rh[(iy - jy + 6) * 13 + (ix - jx + 6)];
            if (shifted && slbl[m] != mylbl) d -= 100.f;
            s[m] = d;
            mx = fmaxf(mx, d);
        }
        float sum = 0.f;
        #pragma unroll
        for (int m = 0; m < 49; m++) {
            float e = __expf(s[m] - mx);
            s[m] = e;
            sum += e;
        }
        float inv = 1.f / sum;
        float o[16];
        #pragma unroll
        for (int d = 0; d < 16; d++) o[d] = 0.f;
        #pragma unroll
        for (int m = 0; m < 49; m++) {
            float p = s[m] * inv;
            float4 v0 = *(const float4*)&vh[m*16+0];
            float4 v1 = *(const float4*)&vh[m*16+4];
            float4 v2 = *(const float4*)&vh[m*16+8];
            float4 v3 = *(const float4*)&vh[m*16+12];
            o[0]+=p*v0.x; o[1]+=p*v0.y; o[2]+=p*v0.z; o[3]+=p*v0.w;
            o[4]+=p*v1.x; o[5]+=p*v1.y; o[6]+=p*v1.z; o[7]+=p*v1.w;
            o[8]+=p*v2.x; o[9]+=p*v2.y; o[10]+=p*v2.z; o[11]+=p*v2.w;
            o[12]+=p*v3.x; o[13]+=p*v3.y; o[14]+=p*v3.z; o[15]+=p*v3.w;
        }
        float* op = outA + ((size_t)bw * 49 + n) * C2 + (h0 + h2) * 16;
        *(float4*)(op+0)  = make_float4(o[0],o[1],o[2],o[3]);
        *(float4*)(op+4)  = make_float4(o[4],o[5],o[6],o[7]);
        *(float4*)(op+8)  = make_float4(o[8],o[9],o[10],o[11]);
        *(float4*)(op+12) = make_float4(o[12],o[13],o[14],o[15]);
    }
}

// ---------------- launch -----------------------------------------------------
extern "C" void kernel_launch(void* const* d_in, const int* in_sizes, int n_in,
                              void* d_out, int out_size) {
    (void)in_sizes; (void)n_in; (void)out_size;
    const float* x     = (const float*)d_in[0];
    const float* up_w  = (const float*)d_in[1];
    const float* up_b  = (const float*)d_in[2];
    const float* bn_g  = (const float*)d_in[3];
    const float* bn_b  = (const float*)d_in[4];
    const float* bn_m  = (const float*)d_in[5];
    const float* bn_v  = (const float*)d_in[6];
    const float* n1g   = (const float*)d_in[7];
    const float* n1b   = (const float*)d_in[8];
    const float* qkvw  = (const float*)d_in[9];
    const float* qkvb  = (const float*)d_in[10];
    const float* projw = (const float*)d_in[11];
    const float* projb = (const float*)d_in[12];
    const float* rel   = (const float*)d_in[13];
    const float* n2g   = (const float*)d_in[14];
    const float* n2b   = (const float*)d_in[15];
    const float* f1w   = (const float*)d_in[16];
    const float* f1b   = (const float*)d_in[17];
    const float* f2w   = (const float*)d_in[18];
    const float* f2b   = (const float*)d_in[19];
    const float* outw  = (const float*)d_in[20];
    const float* outb  = (const float*)d_in[21];
    float* out = (float*)d_out;

    float *bX, *bW, *bA, *bQ, *bH, *wc, *scl, *sft;
    cudaGetSymbolAddress((void**)&bX,  d_bufX);
    cudaGetSymbolAddress((void**)&bW,  d_bufW);
    cudaGetSymbolAddress((void**)&bA,  d_bufA);
    cudaGetSymbolAddress((void**)&bQ,  d_bufQ);
    cudaGetSymbolAddress((void**)&bH,  d_bufH);
    cudaGetSymbolAddress((void**)&wc,  d_wc);
    cudaGetSymbolAddress((void**)&scl, d_cscale);
    cudaGetSymbolAddress((void**)&sft, d_cshift);

    cudaFuncSetAttribute(mma_gemm<ALConv,   StConv>, cudaFuncAttributeMaxDynamicSharedMemorySize, SMEM_BYTES);
    cudaFuncSetAttribute(mma_gemm<ALDirect, StQKV>,  cudaFuncAttributeMaxDynamicSharedMemorySize, SMEM_BYTES);
    cudaFuncSetAttribute(mma_gemm<ALDirect, StProj>, cudaFuncAttributeMaxDynamicSharedMemorySize, SMEM_BYTES);
    cudaFuncSetAttribute(mma_gemm<ALDirect, StGelu>, cudaFuncAttributeMaxDynamicSharedMemorySize, SMEM_BYTES);
    cudaFuncSetAttribute(mma_gemm<ALDirect, StFC2>,  cudaFuncAttributeMaxDynamicSharedMemorySize, SMEM_BYTES);
    cudaFuncSetAttribute(mma_gemm<ALDirect, StOut>,  cudaFuncAttributeMaxDynamicSharedMemorySize, SMEM_BYTES);

    prep_kernel<<<64, 256>>>(up_w, up_b, bn_g, bn_b, bn_m, bn_v);

    for (int p = 0; p < 4; p++) {
        ALConv al; al.in = x; al.py = p >> 1; al.px = p & 1;
        StConv st; st.out = bX; st.scale = scl; st.shift = sft; st.py = p >> 1; st.px = p & 1;
        mma_gemm<<<dim3(196, 1), 256, SMEM_BYTES>>>(al, st, wc + (size_t)p * 96 * 768, 96, 768);
    }

    for (int i = 0; i < 2; i++) {
        int sh = i ? 3 : 0;
        ln_part_kernel<<<25088, 128>>>(bX, bW, n1g + i * 96, n1b + i * 96, sh);

        { ALDirect al; al.A = bW; al.K = 96;
          StQKV st; st.out = bQ; st.bias = qkvb + i * 288;
          mma_gemm<<<dim3(784, 3), 256, SMEM_BYTES>>>(al, st, qkvw + (size_t)i * 288 * 96, 288, 96); }

        attn_kernel<<<dim3(2048, 3), 128>>>(bQ, rel + (size_t)i * 169 * 6, bA, sh);

        { ALDirect al; al.A = bA; al.K = 96;
          StProj st; st.out = bX; st.bias = projb + i * 96; st.shift = sh;
          mma_gemm<<<dim3(784, 1), 256, SMEM_BYTES>>>(al, st, projw + (size_t)i * 96 * 96, 96, 96); }

        ln_plain_kernel<<<25088, 128>>>(bX, bW, n2g + i * 96, n2b + i * 96);

        { ALDirect al; al.A = bW; al.K = 96;
          StGelu st; st.out = bH; st.bias = f1b + i * HID;
          mma_gemm<<<dim3(784, 4), 256, SMEM_BYTES>>>(al, st, f1w + (size_t)i * HID * 96, HID, 96); }

        { ALDirect al; al.A = bH; al.K = HID;
          StFC2 st; st.out = bX; st.bias = f2b + i * 96;
          mma_gemm<<<dim3(784, 1), 256, SMEM_BYTES>>>(al, st, f2w + (size_t)i * 96 * HID, 96, 384); }
    }

    { ALDirect al; al.A = bX; al.K = 96;
      StOut st; st.out = out; st.bias = outb;
      mma_gemm<<<dim3(784, 1), 256, SMEM_BYTES>>>(al, st, outw, 48, 96); }
}